// round 3
// baseline (speedup 1.0000x reference)
#include <cuda_runtime.h>
#include <cfloat>

#define N_NODES 50000
#define N_EDGES 800000
#define F_IN    256
#define H_DIM   128
#define O_DIM   64

// ---------------- device scratch (no allocation allowed) ----------------
__device__ int   g_degi[N_NODES];
__device__ float g_dinv[N_NODES];
__device__ int   g_row_ptr[N_NODES + 1];
__device__ int   g_cursor[N_NODES];
__device__ int   g_csr_src[N_EDGES];
__device__ float g_csr_w[N_EDGES];
__device__ float g_bufA[(size_t)N_NODES * H_DIM];
__device__ float g_bufB[(size_t)N_NODES * H_DIM];

// ---------------- setup kernels ----------------
__global__ void k_init(float* d_out) {
    int i = blockIdx.x * blockDim.x + threadIdx.x;
    if (i < N_NODES) g_degi[i] = 0;
    if (i < O_DIM)   d_out[i] = -FLT_MAX;
}

__global__ void k_hist(const int* __restrict__ dst) {
    int e = blockIdx.x * blockDim.x + threadIdx.x;
    if (e < N_EDGES) atomicAdd(&g_degi[dst[e]], 1);
}

__global__ void k_dinv() {
    int i = blockIdx.x * blockDim.x + threadIdx.x;
    if (i < N_NODES) g_dinv[i] = rsqrtf((float)(g_degi[i] + 1));  // +1 self loop
}

// single-block exclusive scan of g_degi -> g_row_ptr / g_cursor
__global__ void k_scan() {
    __shared__ int sums[1024];
    const int t = threadIdx.x;
    const int chunk = (N_NODES + 1023) / 1024;
    int beg = t * chunk;
    int end = min(beg + chunk, N_NODES);
    int s = 0;
    for (int i = beg; i < end; i++) s += g_degi[i];
    sums[t] = s;
    __syncthreads();
    for (int off = 1; off < 1024; off <<= 1) {
        int add = (t >= off) ? sums[t - off] : 0;
        __syncthreads();
        sums[t] += add;
        __syncthreads();
    }
    int run = (t == 0) ? 0 : sums[t - 1];
    for (int i = beg; i < end; i++) {
        g_row_ptr[i] = run;
        g_cursor[i]  = run;
        run += g_degi[i];
    }
    if (end == N_NODES) g_row_ptr[N_NODES] = run;
}

__global__ void k_scatter(const int* __restrict__ src, const int* __restrict__ dst) {
    int e = blockIdx.x * blockDim.x + threadIdx.x;
    if (e >= N_EDGES) return;
    int s = src[e], d = dst[e];
    int pos = atomicAdd(&g_cursor[d], 1);
    g_csr_src[pos] = s;
    g_csr_w[pos]   = g_dinv[s];   // dinv[dst] factored out, applied per-row
}

// ---------------- SpMM: out[i] = dinv[i]*(sum_e w_e*h[src_e] + dinv[i]*h[i]) + b
// warp per row, 4 floats (float4) per lane, H=128
__global__ void k_spmm(const float* __restrict__ h, const float* __restrict__ bias,
                       float* __restrict__ out) {
    int warp = (blockIdx.x * blockDim.x + threadIdx.x) >> 5;
    if (warp >= N_NODES) return;
    int lane = threadIdx.x & 31;
    const float4* h4 = (const float4*)h;
    float di = g_dinv[warp];
    float4 sv = h4[(size_t)warp * 32 + lane];
    float ax = sv.x * di, ay = sv.y * di, az = sv.z * di, aw = sv.w * di;
    int e    = g_row_ptr[warp];
    int eEnd = g_row_ptr[warp + 1];
    for (; e < eEnd; ++e) {
        int   s = g_csr_src[e];
        float w = g_csr_w[e];
        float4 v = __ldg(&h4[(size_t)s * 32 + lane]);
        ax = fmaf(w, v.x, ax);
        ay = fmaf(w, v.y, ay);
        az = fmaf(w, v.z, az);
        aw = fmaf(w, v.w, aw);
    }
    int cb = lane * 4;
    float4 o;
    o.x = fmaf(ax, di, bias[cb + 0]);
    o.y = fmaf(ay, di, bias[cb + 1]);
    o.z = fmaf(az, di, bias[cb + 2]);
    o.w = fmaf(aw, di, bias[cb + 3]);
    ((float4*)out)[(size_t)warp * 32 + lane] = o;
}

// ---------------- tiled SGEMM: C[n,M] = A[n,K] @ B[K,M] (+bias) ----------------
template <int BM, int BN, int BK>
__global__ void sgemm_kernel(const float* __restrict__ A, const float* __restrict__ B,
                             const float* __restrict__ bias, float* __restrict__ C,
                             int n, int K, int M) {
    __shared__ float As[BK][BM];
    __shared__ float Bs[BK][BN];
    const int tid = threadIdx.x;           // 256 threads
    const int ty  = tid / (BN / 4);        // 0..15
    const int tx  = tid % (BN / 4);        // 0..15
    const int rowBase = blockIdx.x * BM;
    const int colBase = blockIdx.y * BN;

    float acc[4][4];
#pragma unroll
    for (int i = 0; i < 4; i++)
#pragma unroll
        for (int j = 0; j < 4; j++) acc[i][j] = 0.f;

    const int aRow = tid >> 2;             // 0..63
    const int aKq  = (tid & 3) * 4;        // 0,4,8,12
    const int bK   = tid >> 4;             // 0..15
    const int bCq  = (tid & 15) * 4;       // 0..60

    for (int k0 = 0; k0 < K; k0 += BK) {
        float4 av = make_float4(0.f, 0.f, 0.f, 0.f);
        int gr = rowBase + aRow;
        if (gr < n) av = *(const float4*)(A + (size_t)gr * K + k0 + aKq);
        As[aKq + 0][aRow] = av.x;
        As[aKq + 1][aRow] = av.y;
        As[aKq + 2][aRow] = av.z;
        As[aKq + 3][aRow] = av.w;

        float4 bv = *(const float4*)(B + (size_t)(k0 + bK) * M + colBase + bCq);
        *(float4*)&Bs[bK][bCq] = bv;
        __syncthreads();
#pragma unroll
        for (int k = 0; k < BK; k++) {
            float4 ra4 = *(const float4*)&As[k][ty * 4];
            float4 rb4 = *(const float4*)&Bs[k][tx * 4];
            float ra[4] = {ra4.x, ra4.y, ra4.z, ra4.w};
            float rb[4] = {rb4.x, rb4.y, rb4.z, rb4.w};
#pragma unroll
            for (int i = 0; i < 4; i++)
#pragma unroll
                for (int j = 0; j < 4; j++)
                    acc[i][j] = fmaf(ra[i], rb[j], acc[i][j]);
        }
        __syncthreads();
    }
#pragma unroll
    for (int i = 0; i < 4; i++) {
        int gr = rowBase + ty * 4 + i;
        if (gr < n) {
            int gc = colBase + tx * 4;
            float4 o = make_float4(acc[i][0], acc[i][1], acc[i][2], acc[i][3]);
            if (bias) {
                o.x += bias[gc + 0]; o.y += bias[gc + 1];
                o.z += bias[gc + 2]; o.w += bias[gc + 3];
            }
            *(float4*)(C + (size_t)gr * M + gc) = o;
        }
    }
}

// ---------------- global max pool over rows ----------------
__device__ __forceinline__ void atomicMaxFloat(float* addr, float val) {
    if (val >= 0.f) atomicMax((int*)addr, __float_as_int(val));
    else            atomicMin((unsigned int*)addr, __float_as_uint(val));
}

__global__ void k_maxpool(const float* __restrict__ h, float* __restrict__ d_out) {
    int c = threadIdx.x;  // 0..63
    float m = -FLT_MAX;
    for (int r = blockIdx.x; r < N_NODES; r += gridDim.x)
        m = fmaxf(m, h[(size_t)r * O_DIM + c]);
    atomicMaxFloat(&d_out[c], m);
}

// ---------------- launch ----------------
extern "C" void kernel_launch(void* const* d_in, const int* in_sizes, int n_in,
                              void* d_out, int out_size) {
    const float* x  = (const float*)d_in[0];
    const int*   ei = (const int*)d_in[1];
    const float* W0 = (const float*)d_in[3];
    const float* b0 = (const float*)d_in[4];
    const float* W1 = (const float*)d_in[5];
    const float* b1 = (const float*)d_in[6];
    const float* W2 = (const float*)d_in[7];
    const float* b2 = (const float*)d_in[8];
    const float* Wl = (const float*)d_in[9];
    const float* bl = (const float*)d_in[10];
    float* out = (float*)d_out;

    const int* src = ei;             // edge_index[0]
    const int* dst = ei + N_EDGES;   // edge_index[1]

    float *bufA, *bufB;
    cudaGetSymbolAddress((void**)&bufA, g_bufA);
    cudaGetSymbolAddress((void**)&bufB, g_bufB);

    const int TB = 256;
    k_init<<<(N_NODES + TB - 1) / TB, TB>>>(out);
    k_hist<<<(N_EDGES + TB - 1) / TB, TB>>>(dst);
    k_dinv<<<(N_NODES + TB - 1) / TB, TB>>>();
    k_scan<<<1, 1024>>>();
    k_scatter<<<(N_EDGES + TB - 1) / TB, TB>>>(src, dst);

    dim3 gH((N_NODES + 63) / 64, H_DIM / 64);  // 782 x 2
    dim3 gO((N_NODES + 63) / 64, O_DIM / 64);  // 782 x 1
    int spmmBlocks = (N_NODES * 32 + TB - 1) / TB;  // warp per row

    sgemm_kernel<64, 64, 16><<<gH, 256>>>(x, W0, nullptr, bufA, N_NODES, F_IN, H_DIM);
    k_spmm<<<spmmBlocks, TB>>>(bufA, b0, bufB);

    sgemm_kernel<64, 64, 16><<<gH, 256>>>(bufB, W1, nullptr, bufA, N_NODES, H_DIM, H_DIM);
    k_spmm<<<spmmBlocks, TB>>>(bufA, b1, bufB);

    sgemm_kernel<64, 64, 16><<<gH, 256>>>(bufB, W2, nullptr, bufA, N_NODES, H_DIM, H_DIM);
    k_spmm<<<spmmBlocks, TB>>>(bufA, b2, bufB);

    sgemm_kernel<64, 64, 16><<<gO, 256>>>(bufB, Wl, bl, bufA, N_NODES, H_DIM, O_DIM);
    k_maxpool<<<256, O_DIM>>>(bufA, out);
}

// round 5
// speedup vs baseline: 1.2049x; 1.2049x over previous
#include <cuda_runtime.h>
#include <cfloat>

#define N_NODES 50000
#define N_EDGES 800000
#define F_IN    256
#define H_DIM   128
#define O_DIM   64

#define NB_SCAN 128
#define CHUNK   391   // ceil(N_NODES / NB_SCAN)

// ---------------- device scratch (no allocation allowed) ----------------
__device__ int   g_degi[N_NODES];
__device__ float g_dinv[N_NODES];
__device__ int   g_row_ptr[N_NODES + 1];
__device__ int   g_cursor[N_NODES];
__device__ int   g_csr_src[N_EDGES];
__device__ float g_csr_w[N_EDGES];
__device__ int   g_chunk_sum[NB_SCAN];
__device__ int   g_chunk_off[NB_SCAN + 1];
__device__ float g_bufA[(size_t)N_NODES * H_DIM];
__device__ float g_bufB[(size_t)N_NODES * H_DIM];

// ---------------- setup kernels ----------------
__global__ void k_init(float* d_out) {
    int i = blockIdx.x * blockDim.x + threadIdx.x;
    if (i < N_NODES) g_degi[i] = 0;
    if (i < O_DIM)   d_out[i] = -FLT_MAX;
}

__global__ void k_hist(const int* __restrict__ dst) {
    int e4 = blockIdx.x * blockDim.x + threadIdx.x;
    if (e4 * 4 + 3 < N_EDGES) {
        int4 d = ((const int4*)dst)[e4];
        atomicAdd(&g_degi[d.x], 1);
        atomicAdd(&g_degi[d.y], 1);
        atomicAdd(&g_degi[d.z], 1);
        atomicAdd(&g_degi[d.w], 1);
    } else {
        for (int e = e4 * 4; e < N_EDGES; e++) atomicAdd(&g_degi[dst[e]], 1);
    }
}

// per-chunk degree sums + dinv (fused)
__global__ void k_chunk_sum() {
    int b = blockIdx.x, t = threadIdx.x;
    int beg = b * CHUNK, end = min(beg + CHUNK, N_NODES);
    __shared__ int red[256];
    int s = 0;
    for (int i = beg + t; i < end; i += 256) {
        int d = g_degi[i];
        s += d;
        g_dinv[i] = rsqrtf((float)(d + 1));  // +1 self loop
    }
    red[t] = s;
    __syncthreads();
    for (int off = 128; off; off >>= 1) {
        if (t < off) red[t] += red[t + off];
        __syncthreads();
    }
    if (t == 0) g_chunk_sum[b] = red[0];
}

// inclusive scan of 128 chunk sums -> exclusive chunk offsets
__global__ void k_scan_chunks() {
    __shared__ int sh[NB_SCAN];
    int t = threadIdx.x;
    sh[t] = g_chunk_sum[t];
    __syncthreads();
    for (int off = 1; off < NB_SCAN; off <<= 1) {
        int v = (t >= off) ? sh[t - off] : 0;
        __syncthreads();
        sh[t] += v;
        __syncthreads();
    }
    g_chunk_off[t + 1] = sh[t];
    if (t == 0) g_chunk_off[0] = 0;
}

// per-chunk block scan -> row_ptr / cursor
__global__ void k_write_rowptr() {
    int b = blockIdx.x, t = threadIdx.x;
    int beg = b * CHUNK;
    int i = beg + t;
    __shared__ int sh[512];
    int v = (t < CHUNK && i < N_NODES) ? g_degi[i] : 0;
    sh[t] = v;
    __syncthreads();
    for (int off = 1; off < 512; off <<= 1) {
        int u = (t >= off) ? sh[t - off] : 0;
        __syncthreads();
        sh[t] += u;
        __syncthreads();
    }
    if (t < CHUNK && i < N_NODES) {
        int rp = g_chunk_off[b] + sh[t] - v;   // exclusive prefix
        g_row_ptr[i] = rp;
        g_cursor[i]  = rp;
    }
    if (b == NB_SCAN - 1 && t == 0) g_row_ptr[N_NODES] = g_chunk_off[NB_SCAN];
}

__global__ void k_scatter(const int* __restrict__ src, const int* __restrict__ dst) {
    int e = blockIdx.x * blockDim.x + threadIdx.x;
    if (e >= N_EDGES) return;
    int s = src[e], d = dst[e];
    int pos = atomicAdd(&g_cursor[d], 1);
    g_csr_src[pos] = s;
    g_csr_w[pos]   = g_dinv[s];   // dinv[dst] factored out, applied per-row
}

// ---------------- SpMM: out[i] = dinv[i]*(sum_e w_e*h[src_e] + dinv[i]*h[i]) + b
__global__ void k_spmm(const float* __restrict__ h, const float* __restrict__ bias,
                       float* __restrict__ out) {
    int warp = (blockIdx.x * blockDim.x + threadIdx.x) >> 5;
    if (warp >= N_NODES) return;
    int lane = threadIdx.x & 31;
    const float4* h4 = (const float4*)h;
    float di = g_dinv[warp];
    float4 sv = h4[(size_t)warp * 32 + lane];
    float ax = sv.x * di, ay = sv.y * di, az = sv.z * di, aw = sv.w * di;
    int e    = g_row_ptr[warp];
    int eEnd = g_row_ptr[warp + 1];
    for (; e < eEnd; ++e) {
        int   s = g_csr_src[e];
        float w = g_csr_w[e];
        float4 v = __ldg(&h4[(size_t)s * 32 + lane]);
        ax = fmaf(w, v.x, ax);
        ay = fmaf(w, v.y, ay);
        az = fmaf(w, v.z, az);
        aw = fmaf(w, v.w, aw);
    }
    int cb = lane * 4;
    float4 o;
    o.x = fmaf(ax, di, bias[cb + 0]);
    o.y = fmaf(ay, di, bias[cb + 1]);
    o.z = fmaf(az, di, bias[cb + 2]);
    o.w = fmaf(aw, di, bias[cb + 3]);
    ((float4*)out)[(size_t)warp * 32 + lane] = o;
}

// ---------------- 128x128 tile SGEMM, BK=8, 8x8 microtile, M must be 128 ----
__global__ __launch_bounds__(256) void sgemm128(const float* __restrict__ A,
                                                const float* __restrict__ B,
                                                float* __restrict__ C,
                                                int n, int K) {
    const int M = 128;
    __shared__ float As[8][132];
    __shared__ float Bs[8][132];
    const int tid = threadIdx.x;
    const int rowBase = blockIdx.x * 128;

    const int aRow = tid >> 1;          // 0..127
    const int aK   = (tid & 1) * 4;     // 0 or 4
    const int bK   = tid >> 5;          // 0..7
    const int bC   = (tid & 31) * 4;    // 0..124
    const int tx   = tid & 15;
    const int ty   = tid >> 4;

    float acc[8][8];
#pragma unroll
    for (int i = 0; i < 8; i++)
#pragma unroll
        for (int j = 0; j < 8; j++) acc[i][j] = 0.f;

    const bool aValid = (rowBase + aRow) < n;
    const float* Aptr = A + (size_t)(rowBase + aRow) * K;

    for (int k0 = 0; k0 < K; k0 += 8) {
        float4 av = aValid ? *(const float4*)(Aptr + k0 + aK)
                           : make_float4(0.f, 0.f, 0.f, 0.f);
        As[aK + 0][aRow] = av.x;
        As[aK + 1][aRow] = av.y;
        As[aK + 2][aRow] = av.z;
        As[aK + 3][aRow] = av.w;
        *(float4*)&Bs[bK][bC] = *(const float4*)(B + (size_t)(k0 + bK) * M + bC);
        __syncthreads();
#pragma unroll
        for (int k = 0; k < 8; k++) {
            float4 a0 = *(const float4*)&As[k][ty * 4];
            float4 a1 = *(const float4*)&As[k][64 + ty * 4];
            float4 b0 = *(const float4*)&Bs[k][tx * 4];
            float4 b1 = *(const float4*)&Bs[k][64 + tx * 4];
            float a[8]  = {a0.x, a0.y, a0.z, a0.w, a1.x, a1.y, a1.z, a1.w};
            float bb[8] = {b0.x, b0.y, b0.z, b0.w, b1.x, b1.y, b1.z, b1.w};
#pragma unroll
            for (int i = 0; i < 8; i++)
#pragma unroll
                for (int j = 0; j < 8; j++)
                    acc[i][j] = fmaf(a[i], bb[j], acc[i][j]);
        }
        __syncthreads();
    }
#pragma unroll
    for (int i = 0; i < 8; i++) {
        int r = rowBase + ((i < 4) ? (ty * 4 + i) : (64 + ty * 4 + i - 4));
        if (r < n) {
            *(float4*)(C + (size_t)r * M + tx * 4) =
                make_float4(acc[i][0], acc[i][1], acc[i][2], acc[i][3]);
            *(float4*)(C + (size_t)r * M + 64 + tx * 4) =
                make_float4(acc[i][4], acc[i][5], acc[i][6], acc[i][7]);
        }
    }
}

// ---------------- 64x64 tile SGEMM (for the final M=64 layer) ----------------
template <int BM, int BN, int BK>
__global__ void sgemm_kernel(const float* __restrict__ A, const float* __restrict__ B,
                             const float* __restrict__ bias, float* __restrict__ C,
                             int n, int K, int M) {
    __shared__ float As[BK][BM];
    __shared__ float Bs[BK][BN];
    const int tid = threadIdx.x;           // 256 threads
    const int ty  = tid / (BN / 4);
    const int tx  = tid % (BN / 4);
    const int rowBase = blockIdx.x * BM;
    const int colBase = blockIdx.y * BN;

    float acc[4][4];
#pragma unroll
    for (int i = 0; i < 4; i++)
#pragma unroll
        for (int j = 0; j < 4; j++) acc[i][j] = 0.f;

    const int aRow = tid >> 2;
    const int aKq  = (tid & 3) * 4;
    const int bK   = tid >> 4;
    const int bCq  = (tid & 15) * 4;

    for (int k0 = 0; k0 < K; k0 += BK) {
        float4 av = make_float4(0.f, 0.f, 0.f, 0.f);
        int gr = rowBase + aRow;
        if (gr < n) av = *(const float4*)(A + (size_t)gr * K + k0 + aKq);
        As[aKq + 0][aRow] = av.x;
        As[aKq + 1][aRow] = av.y;
        As[aKq + 2][aRow] = av.z;
        As[aKq + 3][aRow] = av.w;

        float4 bv = *(const float4*)(B + (size_t)(k0 + bK) * M + colBase + bCq);
        *(float4*)&Bs[bK][bCq] = bv;
        __syncthreads();
#pragma unroll
        for (int k = 0; k < BK; k++) {
            float4 ra4 = *(const float4*)&As[k][ty * 4];
            float4 rb4 = *(const float4*)&Bs[k][tx * 4];
            float ra[4] = {ra4.x, ra4.y, ra4.z, ra4.w};
            float rb[4] = {rb4.x, rb4.y, rb4.z, rb4.w};
#pragma unroll
            for (int i = 0; i < 4; i++)
#pragma unroll
                for (int j = 0; j < 4; j++)
                    acc[i][j] = fmaf(ra[i], rb[j], acc[i][j]);
        }
        __syncthreads();
    }
#pragma unroll
    for (int i = 0; i < 4; i++) {
        int gr = rowBase + ty * 4 + i;
        if (gr < n) {
            int gc = colBase + tx * 4;
            float4 o = make_float4(acc[i][0], acc[i][1], acc[i][2], acc[i][3]);
            if (bias) {
                o.x += bias[gc + 0]; o.y += bias[gc + 1];
                o.z += bias[gc + 2]; o.w += bias[gc + 3];
            }
            *(float4*)(C + (size_t)gr * M + gc) = o;
        }
    }
}

// ---------------- global max pool over rows ----------------
__device__ __forceinline__ void atomicMaxFloat(float* addr, float val) {
    if (val >= 0.f) atomicMax((int*)addr, __float_as_int(val));
    else            atomicMin((unsigned int*)addr, __float_as_uint(val));
}

__global__ void k_maxpool(const float* __restrict__ h, float* __restrict__ d_out) {
    int c = threadIdx.x;  // 0..63
    float m = -FLT_MAX;
    for (int r = blockIdx.x; r < N_NODES; r += gridDim.x)
        m = fmaxf(m, h[(size_t)r * O_DIM + c]);
    atomicMaxFloat(&d_out[c], m);
}

// ---------------- launch ----------------
extern "C" void kernel_launch(void* const* d_in, const int* in_sizes, int n_in,
                              void* d_out, int out_size) {
    const float* x  = (const float*)d_in[0];
    const int*   ei = (const int*)d_in[1];
    const float* W0 = (const float*)d_in[3];
    const float* b0 = (const float*)d_in[4];
    const float* W1 = (const float*)d_in[5];
    const float* b1 = (const float*)d_in[6];
    const float* W2 = (const float*)d_in[7];
    const float* b2 = (const float*)d_in[8];
    const float* Wl = (const float*)d_in[9];
    const float* bl = (const float*)d_in[10];
    float* out = (float*)d_out;

    const int* src = ei;             // edge_index[0]
    const int* dst = ei + N_EDGES;   // edge_index[1]

    float *bufA, *bufB;
    cudaGetSymbolAddress((void**)&bufA, g_bufA);
    cudaGetSymbolAddress((void**)&bufB, g_bufB);

    const int TB = 256;
    k_init<<<(N_NODES + TB - 1) / TB, TB>>>(out);
    k_hist<<<((N_EDGES / 4) + TB - 1) / TB, TB>>>(dst);
    k_chunk_sum<<<NB_SCAN, 256>>>();
    k_scan_chunks<<<1, NB_SCAN>>>();
    k_write_rowptr<<<NB_SCAN, 512>>>();
    k_scatter<<<(N_EDGES + TB - 1) / TB, TB>>>(src, dst);

    int gemmBlocks = (N_NODES + 127) / 128;               // 391
    dim3 gO((N_NODES + 63) / 64, O_DIM / 64);             // 782 x 1
    int spmmBlocks = (N_NODES * 32 + TB - 1) / TB;        // warp per row

    sgemm128<<<gemmBlocks, 256>>>(x, W0, bufA, N_NODES, F_IN);
    k_spmm<<<spmmBlocks, TB>>>(bufA, b0, bufB);

    sgemm128<<<gemmBlocks, 256>>>(bufB, W1, bufA, N_NODES, H_DIM);
    k_spmm<<<spmmBlocks, TB>>>(bufA, b1, bufB);

    sgemm128<<<gemmBlocks, 256>>>(bufB, W2, bufA, N_NODES, H_DIM);
    k_spmm<<<spmmBlocks, TB>>>(bufA, b2, bufB);

    sgemm_kernel<64, 64, 16><<<gO, 256>>>(bufB, Wl, bl, bufA, N_NODES, H_DIM, O_DIM);
    k_maxpool<<<256, O_DIM>>>(bufA, out);
}

// round 8
// speedup vs baseline: 1.3760x; 1.1420x over previous
#include <cuda_runtime.h>
#include <cfloat>

#define N_NODES 50000
#define N_EDGES 800000
#define F_IN    256
#define H_DIM   128
#define O_DIM   64

#define NB_SCAN 128
#define CHUNK   391   // ceil(N_NODES / NB_SCAN)

// ---------------- device scratch (no allocation allowed) ----------------
__device__ int   g_degi[N_NODES];
__device__ float g_dinv[N_NODES];
__device__ int   g_row_ptr[N_NODES + 1];
__device__ int   g_cursor[N_NODES];
__device__ int   g_csr_src[N_EDGES];
__device__ float g_csr_w[N_EDGES];
__device__ int   g_chunk_sum[NB_SCAN];
__device__ int   g_chunk_off[NB_SCAN + 1];
__device__ float g_bufA[(size_t)N_NODES * H_DIM];
__device__ float g_bufB[(size_t)N_NODES * H_DIM];

// ---------------- packed f32x2 helpers (FFMA2 — sm_103a only via PTX) -----
__device__ __forceinline__ unsigned long long dup2(float f) {
    unsigned long long r;
    asm("mov.b64 %0, {%1, %1};" : "=l"(r) : "f"(f));
    return r;
}
__device__ __forceinline__ void fma2(unsigned long long& d,
                                     unsigned long long a, unsigned long long b) {
    asm("fma.rn.f32x2 %0, %1, %2, %0;" : "+l"(d) : "l"(a), "l"(b));
}
__device__ __forceinline__ float lo32(unsigned long long v) {
    return __uint_as_float((unsigned)v);
}
__device__ __forceinline__ float hi32(unsigned long long v) {
    return __uint_as_float((unsigned)(v >> 32));
}

// ---------------- setup kernels ----------------
__global__ void k_init(float* d_out) {
    int i = blockIdx.x * blockDim.x + threadIdx.x;
    if (i < N_NODES) g_degi[i] = 0;
    if (i < O_DIM)   d_out[i] = -FLT_MAX;
}

__global__ void k_hist(const int* __restrict__ dst) {
    int e4 = blockIdx.x * blockDim.x + threadIdx.x;
    if (e4 * 4 + 3 < N_EDGES) {
        int4 d = ((const int4*)dst)[e4];
        atomicAdd(&g_degi[d.x], 1);
        atomicAdd(&g_degi[d.y], 1);
        atomicAdd(&g_degi[d.z], 1);
        atomicAdd(&g_degi[d.w], 1);
    } else {
        for (int e = e4 * 4; e < N_EDGES; e++) atomicAdd(&g_degi[dst[e]], 1);
    }
}

__global__ void k_chunk_sum() {
    int b = blockIdx.x, t = threadIdx.x;
    int beg = b * CHUNK, end = min(beg + CHUNK, N_NODES);
    __shared__ int red[256];
    int s = 0;
    for (int i = beg + t; i < end; i += 256) {
        int d = g_degi[i];
        s += d;
        g_dinv[i] = rsqrtf((float)(d + 1));  // +1 self loop
    }
    red[t] = s;
    __syncthreads();
    for (int off = 128; off; off >>= 1) {
        if (t < off) red[t] += red[t + off];
        __syncthreads();
    }
    if (t == 0) g_chunk_sum[b] = red[0];
}

__global__ void k_scan_chunks() {
    __shared__ int sh[NB_SCAN];
    int t = threadIdx.x;
    sh[t] = g_chunk_sum[t];
    __syncthreads();
    for (int off = 1; off < NB_SCAN; off <<= 1) {
        int v = (t >= off) ? sh[t - off] : 0;
        __syncthreads();
        sh[t] += v;
        __syncthreads();
    }
    g_chunk_off[t + 1] = sh[t];
    if (t == 0) g_chunk_off[0] = 0;
}

__global__ void k_write_rowptr() {
    int b = blockIdx.x, t = threadIdx.x;
    int beg = b * CHUNK;
    int i = beg + t;
    __shared__ int sh[512];
    int v = (t < CHUNK && i < N_NODES) ? g_degi[i] : 0;
    sh[t] = v;
    __syncthreads();
    for (int off = 1; off < 512; off <<= 1) {
        int u = (t >= off) ? sh[t - off] : 0;
        __syncthreads();
        sh[t] += u;
        __syncthreads();
    }
    if (t < CHUNK && i < N_NODES) {
        int rp = g_chunk_off[b] + sh[t] - v;
        g_row_ptr[i] = rp;
        g_cursor[i]  = rp;
    }
    if (b == NB_SCAN - 1 && t == 0) g_row_ptr[N_NODES] = g_chunk_off[NB_SCAN];
}

__global__ void k_scatter(const int* __restrict__ src, const int* __restrict__ dst) {
    int e = blockIdx.x * blockDim.x + threadIdx.x;
    if (e >= N_EDGES) return;
    int s = src[e], d = dst[e];
    int pos = atomicAdd(&g_cursor[d], 1);
    g_csr_src[pos] = s;
    g_csr_w[pos]   = g_dinv[s];
}

// ---------------- SpMM: out[i] = dinv[i]*(sum w_e*h[src_e] + dinv[i]*h[i]) + b
__global__ void k_spmm(const float* __restrict__ h, const float* __restrict__ bias,
                       float* __restrict__ out) {
    int warp = (blockIdx.x * blockDim.x + threadIdx.x) >> 5;
    if (warp >= N_NODES) return;
    int lane = threadIdx.x & 31;
    const float4* h4 = (const float4*)h;
    float di = g_dinv[warp];
    float4 sv = h4[(size_t)warp * 32 + lane];
    float ax = sv.x * di, ay = sv.y * di, az = sv.z * di, aw = sv.w * di;
    int e    = g_row_ptr[warp];
    int eEnd = g_row_ptr[warp + 1];
    // unroll-2 for MLP
    for (; e + 1 < eEnd; e += 2) {
        int   s0 = g_csr_src[e],   s1 = g_csr_src[e + 1];
        float w0 = g_csr_w[e],     w1 = g_csr_w[e + 1];
        float4 v0 = __ldg(&h4[(size_t)s0 * 32 + lane]);
        float4 v1 = __ldg(&h4[(size_t)s1 * 32 + lane]);
        ax = fmaf(w0, v0.x, ax); ay = fmaf(w0, v0.y, ay);
        az = fmaf(w0, v0.z, az); aw = fmaf(w0, v0.w, aw);
        ax = fmaf(w1, v1.x, ax); ay = fmaf(w1, v1.y, ay);
        az = fmaf(w1, v1.z, az); aw = fmaf(w1, v1.w, aw);
    }
    if (e < eEnd) {
        int   s = g_csr_src[e];
        float w = g_csr_w[e];
        float4 v = __ldg(&h4[(size_t)s * 32 + lane]);
        ax = fmaf(w, v.x, ax); ay = fmaf(w, v.y, ay);
        az = fmaf(w, v.z, az); aw = fmaf(w, v.w, aw);
    }
    int cb = lane * 4;
    float4 o;
    o.x = fmaf(ax, di, bias[cb + 0]);
    o.y = fmaf(ay, di, bias[cb + 1]);
    o.z = fmaf(az, di, bias[cb + 2]);
    o.w = fmaf(aw, di, bias[cb + 3]);
    ((float4*)out)[(size_t)warp * 32 + lane] = o;
}

// ---------------- 128x128 tile SGEMM, BK=8, 8x8 microtile, FFMA2 ----------
__global__ __launch_bounds__(256) void sgemm128(const float* __restrict__ A,
                                                const float* __restrict__ B,
                                                float* __restrict__ C,
                                                int n, int K) {
    const int M = 128;
    __shared__ float As[8][132];
    __shared__ float Bs[8][132];
    const int tid = threadIdx.x;
    const int rowBase = blockIdx.x * 128;

    const int aRow = tid >> 1;          // 0..127
    const int aK   = (tid & 1) * 4;     // 0 or 4
    const int bK   = tid >> 5;          // 0..7
    const int bC   = (tid & 31) * 4;    // 0..124
    const int tx   = tid & 15;
    const int ty   = tid >> 4;

    // acc2[pair][col]: pair p covers rows {2p_lo, 2p_lo+1} of this thread's 8 rows
    unsigned long long acc2[4][8];
#pragma unroll
    for (int p = 0; p < 4; p++)
#pragma unroll
        for (int j = 0; j < 8; j++) acc2[p][j] = 0ull;

    const bool aValid = (rowBase + aRow) < n;
    const float* Aptr = A + (size_t)(rowBase + aRow) * K;

    for (int k0 = 0; k0 < K; k0 += 8) {
        float4 av = aValid ? *(const float4*)(Aptr + k0 + aK)
                           : make_float4(0.f, 0.f, 0.f, 0.f);
        As[aK + 0][aRow] = av.x;
        As[aK + 1][aRow] = av.y;
        As[aK + 2][aRow] = av.z;
        As[aK + 3][aRow] = av.w;
        *(float4*)&Bs[bK][bC] = *(const float4*)(B + (size_t)(k0 + bK) * M + bC);
        __syncthreads();
#pragma unroll
        for (int k = 0; k < 8; k++) {
            // a-pairs come packed directly from row-contiguous smem
            ulonglong2 aA = *(const ulonglong2*)&As[k][ty * 4];        // rows ty*4+{0,1},{2,3}
            ulonglong2 aB = *(const ulonglong2*)&As[k][64 + ty * 4];   // rows 64+ty*4+...
            float4 b0 = *(const float4*)&Bs[k][tx * 4];
            float4 b1 = *(const float4*)&Bs[k][64 + tx * 4];
            unsigned long long ap[4] = {aA.x, aA.y, aB.x, aB.y};
            unsigned long long bd[8] = {dup2(b0.x), dup2(b0.y), dup2(b0.z), dup2(b0.w),
                                        dup2(b1.x), dup2(b1.y), dup2(b1.z), dup2(b1.w)};
#pragma unroll
            for (int p = 0; p < 4; p++)
#pragma unroll
                for (int j = 0; j < 8; j++)
                    fma2(acc2[p][j], ap[p], bd[j]);
        }
        __syncthreads();
    }
    // epilogue: unpack pairs. pair p -> rows: base + 2*(p%2) offset within group
#pragma unroll
    for (int p = 0; p < 4; p++) {
        int rOff = (p < 2) ? (ty * 4 + p * 2) : (64 + ty * 4 + (p - 2) * 2);
        int rLo = rowBase + rOff;
        int rHi = rLo + 1;
        if (rLo < n) {
            *(float4*)(C + (size_t)rLo * M + tx * 4) =
                make_float4(lo32(acc2[p][0]), lo32(acc2[p][1]), lo32(acc2[p][2]), lo32(acc2[p][3]));
            *(float4*)(C + (size_t)rLo * M + 64 + tx * 4) =
                make_float4(lo32(acc2[p][4]), lo32(acc2[p][5]), lo32(acc2[p][6]), lo32(acc2[p][7]));
        }
        if (rHi < n) {
            *(float4*)(C + (size_t)rHi * M + tx * 4) =
                make_float4(hi32(acc2[p][0]), hi32(acc2[p][1]), hi32(acc2[p][2]), hi32(acc2[p][3]));
            *(float4*)(C + (size_t)rHi * M + 64 + tx * 4) =
                make_float4(hi32(acc2[p][4]), hi32(acc2[p][5]), hi32(acc2[p][6]), hi32(acc2[p][7]));
        }
    }
}

// ---------------- fused final GEMM (K=128 -> O=64) + global max pool ------
__device__ __forceinline__ void atomicMaxFloat(float* addr, float val) {
    if (val >= 0.f) atomicMax((int*)addr, __float_as_int(val));
    else            atomicMin((unsigned int*)addr, __float_as_uint(val));
}

__global__ __launch_bounds__(256) void k_gemm_maxpool(const float* __restrict__ A,
                                                      const float* __restrict__ B,
                                                      const float* __restrict__ bias,
                                                      float* __restrict__ d_out,
                                                      int n) {
    const int K = H_DIM, M = O_DIM, BM = 64, BK = 16;
    __shared__ float As[BK][BM];
    __shared__ float Bs[BK][M];
    __shared__ float shmax[16][M];
    const int tid = threadIdx.x;
    const int ty  = tid / 16;
    const int tx  = tid % 16;
    const int rowBase = blockIdx.x * BM;

    float acc[4][4];
#pragma unroll
    for (int i = 0; i < 4; i++)
#pragma unroll
        for (int j = 0; j < 4; j++) acc[i][j] = 0.f;

    const int aRow = tid >> 2;
    const int aKq  = (tid & 3) * 4;
    const int bK   = tid >> 4;
    const int bCq  = (tid & 15) * 4;

    for (int k0 = 0; k0 < K; k0 += BK) {
        float4 av = make_float4(0.f, 0.f, 0.f, 0.f);
        int gr = rowBase + aRow;
        if (gr < n) av = *(const float4*)(A + (size_t)gr * K + k0 + aKq);
        As[aKq + 0][aRow] = av.x;
        As[aKq + 1][aRow] = av.y;
        As[aKq + 2][aRow] = av.z;
        As[aKq + 3][aRow] = av.w;
        *(float4*)&Bs[bK][bCq] = *(const float4*)(B + (size_t)(k0 + bK) * M + bCq);
        __syncthreads();
#pragma unroll
        for (int k = 0; k < BK; k++) {
            float4 ra4 = *(const float4*)&As[k][ty * 4];
            float4 rb4 = *(const float4*)&Bs[k][tx * 4];
            float ra[4] = {ra4.x, ra4.y, ra4.z, ra4.w};
            float rb[4] = {rb4.x, rb4.y, rb4.z, rb4.w};
#pragma unroll
            for (int i = 0; i < 4; i++)
#pragma unroll
                for (int j = 0; j < 4; j++)
                    acc[i][j] = fmaf(ra[i], rb[j], acc[i][j]);
        }
        __syncthreads();
    }
    // column-max over this thread's 4 rows (invalid rows excluded), + bias
#pragma unroll
    for (int j = 0; j < 4; j++) {
        int gc = tx * 4 + j;
        float bj = bias[gc];
        float m = -FLT_MAX;
#pragma unroll
        for (int i = 0; i < 4; i++) {
            int gr = rowBase + ty * 4 + i;
            if (gr < n) m = fmaxf(m, acc[i][j] + bj);
        }
        shmax[ty][gc] = m;
    }
    __syncthreads();
    if (tid < M) {
        float m = -FLT_MAX;
#pragma unroll
        for (int t = 0; t < 16; t++) m = fmaxf(m, shmax[t][tid]);
        atomicMaxFloat(&d_out[tid], m);
    }
}

// ---------------- launch ----------------
extern "C" void kernel_launch(void* const* d_in, const int* in_sizes, int n_in,
                              void* d_out, int out_size) {
    const float* x  = (const float*)d_in[0];
    const int*   ei = (const int*)d_in[1];
    const float* W0 = (const float*)d_in[3];
    const float* b0 = (const float*)d_in[4];
    const float* W1 = (const float*)d_in[5];
    const float* b1 = (const float*)d_in[6];
    const float* W2 = (const float*)d_in[7];
    const float* b2 = (const float*)d_in[8];
    const float* Wl = (const float*)d_in[9];
    const float* bl = (const float*)d_in[10];
    float* out = (float*)d_out;

    const int* src = ei;             // edge_index[0]
    const int* dst = ei + N_EDGES;   // edge_index[1]

    float *bufA, *bufB;
    cudaGetSymbolAddress((void**)&bufA, g_bufA);
    cudaGetSymbolAddress((void**)&bufB, g_bufB);

    const int TB = 256;
    k_init<<<(N_NODES + TB - 1) / TB, TB>>>(out);
    k_hist<<<((N_EDGES / 4) + TB - 1) / TB, TB>>>(dst);
    k_chunk_sum<<<NB_SCAN, 256>>>();
    k_scan_chunks<<<1, NB_SCAN>>>();
    k_write_rowptr<<<NB_SCAN, 512>>>();
    k_scatter<<<(N_EDGES + TB - 1) / TB, TB>>>(src, dst);

    int gemmBlocks = (N_NODES + 127) / 128;               // 391
    int spmmBlocks = (N_NODES * 32 + TB - 1) / TB;        // warp per row

    sgemm128<<<gemmBlocks, 256>>>(x, W0, bufA, N_NODES, F_IN);
    k_spmm<<<spmmBlocks, TB>>>(bufA, b0, bufB);

    sgemm128<<<gemmBlocks, 256>>>(bufB, W1, bufA, N_NODES, H_DIM);
    k_spmm<<<spmmBlocks, TB>>>(bufA, b1, bufB);

    sgemm128<<<gemmBlocks, 256>>>(bufB, W2, bufA, N_NODES, H_DIM);
    k_spmm<<<spmmBlocks, TB>>>(bufA, b2, bufB);

    k_gemm_maxpool<<<(N_NODES + 63) / 64, 256>>>(bufB, Wl, bl, out, N_NODES);
}

// round 12
// speedup vs baseline: 1.5874x; 1.1536x over previous
#include <cuda_runtime.h>
#include <cfloat>
#include <cstdint>

#define N_NODES 50000
#define N_EDGES 800000
#define F_IN    256
#define H_DIM   128
#define O_DIM   64

#define NB_SCAN 128
#define CHUNK   391   // ceil(N_NODES / NB_SCAN)

// ---------------- device scratch (no allocation allowed) ----------------
__device__ int   g_degi[N_NODES];
__device__ float g_dinv[N_NODES];
__device__ int   g_row_ptr[N_NODES + 1];
__device__ int   g_cursor[N_NODES];
__device__ int   g_csr_src[N_EDGES];
__device__ float g_csr_w[N_EDGES];
__device__ int   g_chunk_sum[NB_SCAN];
__device__ int   g_chunk_off[NB_SCAN + 1];
__device__ float g_bufA[(size_t)N_NODES * H_DIM];
__device__ float g_bufB[(size_t)N_NODES * H_DIM];

// ---------------- packed f32x2 helpers (FFMA2 — sm_103 via PTX) ----------
__device__ __forceinline__ unsigned long long dup2(float f) {
    unsigned long long r;
    asm("mov.b64 %0, {%1, %1};" : "=l"(r) : "f"(f));
    return r;
}
__device__ __forceinline__ void fma2(unsigned long long& d,
                                     unsigned long long a, unsigned long long b) {
    asm("fma.rn.f32x2 %0, %1, %2, %0;" : "+l"(d) : "l"(a), "l"(b));
}
__device__ __forceinline__ float lo32(unsigned long long v) {
    return __uint_as_float((unsigned)v);
}
__device__ __forceinline__ float hi32(unsigned long long v) {
    return __uint_as_float((unsigned)(v >> 32));
}

// ---------------- setup kernels ----------------
__global__ void k_init(float* d_out) {
    int i = blockIdx.x * blockDim.x + threadIdx.x;
    if (i < N_NODES) g_degi[i] = 0;
    if (i < O_DIM)   d_out[i] = -FLT_MAX;
}

__global__ void k_hist(const int* __restrict__ dst) {
    int e4 = blockIdx.x * blockDim.x + threadIdx.x;
    if (e4 * 4 + 3 < N_EDGES) {
        int4 d = ((const int4*)dst)[e4];
        atomicAdd(&g_degi[d.x], 1);
        atomicAdd(&g_degi[d.y], 1);
        atomicAdd(&g_degi[d.z], 1);
        atomicAdd(&g_degi[d.w], 1);
    } else {
        for (int e = e4 * 4; e < N_EDGES; e++) atomicAdd(&g_degi[dst[e]], 1);
    }
}

__global__ void k_chunk_sum() {
    int b = blockIdx.x, t = threadIdx.x;
    int beg = b * CHUNK, end = min(beg + CHUNK, N_NODES);
    __shared__ int red[256];
    int s = 0;
    for (int i = beg + t; i < end; i += 256) {
        int d = g_degi[i];
        s += d;
        g_dinv[i] = rsqrtf((float)(d + 1));  // +1 self loop
    }
    red[t] = s;
    __syncthreads();
    for (int off = 128; off; off >>= 1) {
        if (t < off) red[t] += red[t + off];
        __syncthreads();
    }
    if (t == 0) g_chunk_sum[b] = red[0];
}

__global__ void k_scan_chunks() {
    __shared__ int sh[NB_SCAN];
    int t = threadIdx.x;
    sh[t] = g_chunk_sum[t];
    __syncthreads();
    for (int off = 1; off < NB_SCAN; off <<= 1) {
        int v = (t >= off) ? sh[t - off] : 0;
        __syncthreads();
        sh[t] += v;
        __syncthreads();
    }
    g_chunk_off[t + 1] = sh[t];
    if (t == 0) g_chunk_off[0] = 0;
}

__global__ void k_write_rowptr() {
    int b = blockIdx.x, t = threadIdx.x;
    int beg = b * CHUNK;
    int i = beg + t;
    __shared__ int sh[512];
    int v = (t < CHUNK && i < N_NODES) ? g_degi[i] : 0;
    sh[t] = v;
    __syncthreads();
    for (int off = 1; off < 512; off <<= 1) {
        int u = (t >= off) ? sh[t - off] : 0;
        __syncthreads();
        sh[t] += u;
        __syncthreads();
    }
    if (t < CHUNK && i < N_NODES) {
        int rp = g_chunk_off[b] + sh[t] - v;
        g_row_ptr[i] = rp;
        g_cursor[i]  = rp;
    }
    if (b == NB_SCAN - 1 && t == 0) g_row_ptr[N_NODES] = g_chunk_off[NB_SCAN];
}

__global__ void k_scatter(const int* __restrict__ src, const int* __restrict__ dst) {
    int e = blockIdx.x * blockDim.x + threadIdx.x;
    if (e >= N_EDGES) return;
    int s = src[e], d = dst[e];
    int pos = atomicAdd(&g_cursor[d], 1);
    g_csr_src[pos] = s;
    g_csr_w[pos]   = g_dinv[s];
}

// ---------------- SpMM: out[i] = dinv[i]*(sum w_e*h[src_e] + dinv[i]*h[i]) + b
__global__ void k_spmm(const float* __restrict__ h, const float* __restrict__ bias,
                       float* __restrict__ out) {
    int warp = (blockIdx.x * blockDim.x + threadIdx.x) >> 5;
    if (warp >= N_NODES) return;
    int lane = threadIdx.x & 31;
    const float4* h4 = (const float4*)h;
    float di = g_dinv[warp];
    float4 sv = h4[(size_t)warp * 32 + lane];
    float ax = sv.x * di, ay = sv.y * di, az = sv.z * di, aw = sv.w * di;
    int e    = g_row_ptr[warp];
    int eEnd = g_row_ptr[warp + 1];
    for (; e + 1 < eEnd; e += 2) {
        int   s0 = g_csr_src[e],   s1 = g_csr_src[e + 1];
        float w0 = g_csr_w[e],     w1 = g_csr_w[e + 1];
        float4 v0 = __ldg(&h4[(size_t)s0 * 32 + lane]);
        float4 v1 = __ldg(&h4[(size_t)s1 * 32 + lane]);
        ax = fmaf(w0, v0.x, ax); ay = fmaf(w0, v0.y, ay);
        az = fmaf(w0, v0.z, az); aw = fmaf(w0, v0.w, aw);
        ax = fmaf(w1, v1.x, ax); ay = fmaf(w1, v1.y, ay);
        az = fmaf(w1, v1.z, az); aw = fmaf(w1, v1.w, aw);
    }
    if (e < eEnd) {
        int   s = g_csr_src[e];
        float w = g_csr_w[e];
        float4 v = __ldg(&h4[(size_t)s * 32 + lane]);
        ax = fmaf(w, v.x, ax); ay = fmaf(w, v.y, ay);
        az = fmaf(w, v.z, az); aw = fmaf(w, v.w, aw);
    }
    int cb = lane * 4;
    float4 o;
    o.x = fmaf(ax, di, bias[cb + 0]);
    o.y = fmaf(ay, di, bias[cb + 1]);
    o.z = fmaf(az, di, bias[cb + 2]);
    o.w = fmaf(aw, di, bias[cb + 3]);
    ((float4*)out)[(size_t)warp * 32 + lane] = o;
}

// ------ 128x128 tile SGEMM, BK=16, double-buffered, 8x8 microtile, FFMA2 ------
__global__ __launch_bounds__(256, 2) void sgemm128(const float* __restrict__ A,
                                                   const float* __restrict__ B,
                                                   float* __restrict__ C,
                                                   int n, int K) {
    const int M = 128;
    __shared__ float As[2][16][132];
    __shared__ float Bs[2][16][132];
    const int tid = threadIdx.x;
    const int rowBase = blockIdx.x * 128;

    const int aRow = tid >> 1;          // 0..127
    const int aK   = (tid & 1) * 8;     // 0 or 8
    const int bK   = tid >> 4;          // 0..15
    const int bC   = (tid & 15) * 8;    // 0..120
    const int tx   = tid & 15;
    const int ty   = tid >> 4;

    unsigned long long acc2[4][8];
#pragma unroll
    for (int p = 0; p < 4; p++)
#pragma unroll
        for (int j = 0; j < 8; j++) acc2[p][j] = 0ull;

    const bool aValid = (rowBase + aRow) < n;
    const float* Aptr = A + (size_t)(rowBase + aRow) * K;
    const float* Bptr = B + (size_t)bK * M + bC;

    const int NIT = K / 16;

    // prologue: load tile 0 into buffer 0
    {
        float4 a0 = aValid ? *(const float4*)(Aptr + aK)
                           : make_float4(0.f, 0.f, 0.f, 0.f);
        float4 a1 = aValid ? *(const float4*)(Aptr + aK + 4)
                           : make_float4(0.f, 0.f, 0.f, 0.f);
        As[0][aK + 0][aRow] = a0.x; As[0][aK + 1][aRow] = a0.y;
        As[0][aK + 2][aRow] = a0.z; As[0][aK + 3][aRow] = a0.w;
        As[0][aK + 4][aRow] = a1.x; As[0][aK + 5][aRow] = a1.y;
        As[0][aK + 6][aRow] = a1.z; As[0][aK + 7][aRow] = a1.w;
        *(float4*)&Bs[0][bK][bC]     = *(const float4*)(Bptr);
        *(float4*)&Bs[0][bK][bC + 4] = *(const float4*)(Bptr + 4);
    }
    __syncthreads();

    for (int it = 0; it < NIT; it++) {
        const int cur = it & 1, nxt = cur ^ 1;
        float4 pa0, pa1, pb0, pb1;
        const bool hasNext = (it + 1) < NIT;
        if (hasNext) {
            int k0 = (it + 1) * 16;
            pa0 = aValid ? *(const float4*)(Aptr + k0 + aK)
                         : make_float4(0.f, 0.f, 0.f, 0.f);
            pa1 = aValid ? *(const float4*)(Aptr + k0 + aK + 4)
                         : make_float4(0.f, 0.f, 0.f, 0.f);
            pb0 = *(const float4*)(Bptr + (size_t)k0 * M);
            pb1 = *(const float4*)(Bptr + (size_t)k0 * M + 4);
        }
#pragma unroll
        for (int k = 0; k < 16; k++) {
            ulonglong2 aA = *(const ulonglong2*)&As[cur][k][ty * 4];
            ulonglong2 aB = *(const ulonglong2*)&As[cur][k][64 + ty * 4];
            float4 b0 = *(const float4*)&Bs[cur][k][tx * 4];
            float4 b1 = *(const float4*)&Bs[cur][k][64 + tx * 4];
            unsigned long long ap[4] = {aA.x, aA.y, aB.x, aB.y};
            unsigned long long bd[8] = {dup2(b0.x), dup2(b0.y), dup2(b0.z), dup2(b0.w),
                                        dup2(b1.x), dup2(b1.y), dup2(b1.z), dup2(b1.w)};
#pragma unroll
            for (int p = 0; p < 4; p++)
#pragma unroll
                for (int j = 0; j < 8; j++)
                    fma2(acc2[p][j], ap[p], bd[j]);
        }
        if (hasNext) {
            As[nxt][aK + 0][aRow] = pa0.x; As[nxt][aK + 1][aRow] = pa0.y;
            As[nxt][aK + 2][aRow] = pa0.z; As[nxt][aK + 3][aRow] = pa0.w;
            As[nxt][aK + 4][aRow] = pa1.x; As[nxt][aK + 5][aRow] = pa1.y;
            As[nxt][aK + 6][aRow] = pa1.z; As[nxt][aK + 7][aRow] = pa1.w;
            *(float4*)&Bs[nxt][bK][bC]     = pb0;
            *(float4*)&Bs[nxt][bK][bC + 4] = pb1;
        }
        __syncthreads();
    }

#pragma unroll
    for (int p = 0; p < 4; p++) {
        int rOff = (p < 2) ? (ty * 4 + p * 2) : (64 + ty * 4 + (p - 2) * 2);
        int rLo = rowBase + rOff;
        int rHi = rLo + 1;
        if (rLo < n) {
            *(float4*)(C + (size_t)rLo * M + tx * 4) =
                make_float4(lo32(acc2[p][0]), lo32(acc2[p][1]), lo32(acc2[p][2]), lo32(acc2[p][3]));
            *(float4*)(C + (size_t)rLo * M + 64 + tx * 4) =
                make_float4(lo32(acc2[p][4]), lo32(acc2[p][5]), lo32(acc2[p][6]), lo32(acc2[p][7]));
        }
        if (rHi < n) {
            *(float4*)(C + (size_t)rHi * M + tx * 4) =
                make_float4(hi32(acc2[p][0]), hi32(acc2[p][1]), hi32(acc2[p][2]), hi32(acc2[p][3]));
            *(float4*)(C + (size_t)rHi * M + 64 + tx * 4) =
                make_float4(hi32(acc2[p][4]), hi32(acc2[p][5]), hi32(acc2[p][6]), hi32(acc2[p][7]));
        }
    }
}

// ---------------- fused final GEMM (K=128 -> O=64) + global max pool ------
__device__ __forceinline__ void atomicMaxFloat(float* addr, float val) {
    if (val >= 0.f) atomicMax((int*)addr, __float_as_int(val));
    else            atomicMin((unsigned int*)addr, __float_as_uint(val));
}

__global__ __launch_bounds__(256) void k_gemm_maxpool(const float* __restrict__ A,
                                                      const float* __restrict__ B,
                                                      const float* __restrict__ bias,
                                                      float* __restrict__ d_out,
                                                      int n) {
    const int K = H_DIM, M = O_DIM, BM = 64, BK = 16;
    __shared__ float As[BK][BM];
    __shared__ float Bs[BK][M];
    __shared__ float shmax[16][M];
    const int tid = threadIdx.x;
    const int ty  = tid / 16;
    const int tx  = tid % 16;
    const int rowBase = blockIdx.x * BM;

    float acc[4][4];
#pragma unroll
    for (int i = 0; i < 4; i++)
#pragma unroll
        for (int j = 0; j < 4; j++) acc[i][j] = 0.f;

    const int aRow = tid >> 2;
    const int aKq  = (tid & 3) * 4;
    const int bK   = tid >> 4;
    const int bCq  = (tid & 15) * 4;

    for (int k0 = 0; k0 < K; k0 += BK) {
        float4 av = make_float4(0.f, 0.f, 0.f, 0.f);
        int gr = rowBase + aRow;
        if (gr < n) av = *(const float4*)(A + (size_t)gr * K + k0 + aKq);
        As[aKq + 0][aRow] = av.x;
        As[aKq + 1][aRow] = av.y;
        As[aKq + 2][aRow] = av.z;
        As[aKq + 3][aRow] = av.w;
        *(float4*)&Bs[bK][bCq] = *(const float4*)(B + (size_t)(k0 + bK) * M + bCq);
        __syncthreads();
#pragma unroll
        for (int k = 0; k < BK; k++) {
            float4 ra4 = *(const float4*)&As[k][ty * 4];
            float4 rb4 = *(const float4*)&Bs[k][tx * 4];
            float ra[4] = {ra4.x, ra4.y, ra4.z, ra4.w};
            float rb[4] = {rb4.x, rb4.y, rb4.z, rb4.w};
#pragma unroll
            for (int i = 0; i < 4; i++)
#pragma unroll
                for (int j = 0; j < 4; j++)
                    acc[i][j] = fmaf(ra[i], rb[j], acc[i][j]);
        }
        __syncthreads();
    }
#pragma unroll
    for (int j = 0; j < 4; j++) {
        int gc = tx * 4 + j;
        float bj = bias[gc];
        float m = -FLT_MAX;
#pragma unroll
        for (int i = 0; i < 4; i++) {
            int gr = rowBase + ty * 4 + i;
            if (gr < n) m = fmaxf(m, acc[i][j] + bj);
        }
        shmax[ty][gc] = m;
    }
    __syncthreads();
    if (tid < M) {
        float m = -FLT_MAX;
#pragma unroll
        for (int t = 0; t < 16; t++) m = fmaxf(m, shmax[t][tid]);
        atomicMaxFloat(&d_out[tid], m);
    }
}

// ---------------- launch ----------------
extern "C" void kernel_launch(void* const* d_in, const int* in_sizes, int n_in,
                              void* d_out, int out_size) {
    const float* x  = (const float*)d_in[0];
    const int*   ei = (const int*)d_in[1];
    const float* W0 = (const float*)d_in[3];
    const float* b0 = (const float*)d_in[4];
    const float* W1 = (const float*)d_in[5];
    const float* b1 = (const float*)d_in[6];
    const float* W2 = (const float*)d_in[7];
    const float* b2 = (const float*)d_in[8];
    const float* Wl = (const float*)d_in[9];
    const float* bl = (const float*)d_in[10];
    float* out = (float*)d_out;

    const int* src = ei;             // edge_index[0]
    const int* dst = ei + N_EDGES;   // edge_index[1]

    float *bufA, *bufB;
    cudaGetSymbolAddress((void**)&bufA, g_bufA);
    cudaGetSymbolAddress((void**)&bufB, g_bufB);

    const int TB = 256;
    int gemmBlocks = (N_NODES + 127) / 128;               // 391
    int spmmBlocks = (N_NODES * 32 + TB - 1) / TB;        // warp per row

    // fork: prep chain on side stream, GEMM0 on main (capture) stream
    cudaStream_t s2;
    cudaStreamCreateWithFlags(&s2, cudaStreamNonBlocking);
    cudaEvent_t evF, evJ;
    cudaEventCreateWithFlags(&evF, cudaEventDisableTiming);
    cudaEventCreateWithFlags(&evJ, cudaEventDisableTiming);

    cudaEventRecord(evF, 0);
    cudaStreamWaitEvent(s2, evF, 0);

    k_init<<<(N_NODES + TB - 1) / TB, TB, 0, s2>>>(out);
    k_hist<<<((N_EDGES / 4) + TB - 1) / TB, TB, 0, s2>>>(dst);
    k_chunk_sum<<<NB_SCAN, 256, 0, s2>>>();
    k_scan_chunks<<<1, NB_SCAN, 0, s2>>>();
    k_write_rowptr<<<NB_SCAN, 512, 0, s2>>>();
    k_scatter<<<(N_EDGES + TB - 1) / TB, TB, 0, s2>>>(src, dst);
    cudaEventRecord(evJ, s2);

    // overlaps with the prep chain above
    sgemm128<<<gemmBlocks, 256>>>(x, W0, bufA, N_NODES, F_IN);

    // join: SpMM needs CSR + dinv + GEMM0 output
    cudaStreamWaitEvent(0, evJ, 0);

    k_spmm<<<spmmBlocks, TB>>>(bufA, b0, bufB);

    sgemm128<<<gemmBlocks, 256>>>(bufB, W1, bufA, N_NODES, H_DIM);
    k_spmm<<<spmmBlocks, TB>>>(bufA, b1, bufB);

    sgemm128<<<gemmBlocks, 256>>>(bufB, W2, bufA, N_NODES, H_DIM);
    k_spmm<<<spmmBlocks, TB>>>(bufA, b2, bufB);

    k_gemm_maxpool<<<(N_NODES + 63) / 64, 256>>>(bufB, Wl, bl, out, N_NODES);
}